// round 9
// baseline (speedup 1.0000x reference)
#include <cuda_runtime.h>

// ---------------- problem constants ----------------
#define BB   4
#define NPG  2048        // coarse nodes per graph
#define MM   65536       // skip nodes
#define MPG  16384
#define EE   131072      // edges
#define EPG  32768
#define TT   16          // tokens per graph
#define FIN  16
#define GDIM 1024
#define EMB  64
#define NH   4
#define HD   16
#define CI   32
#define PDIM 67          // 3 + 64
#define P2N  34          // padded p-pairs (68/2)

typedef unsigned long long ull;

// ---------------- device scratch (no cudaMalloc allowed) ----------------
__device__ float d_pseudo[EE * PDIM];     // 35 MB
__device__ float d_h0[MM * CI];
__device__ float d_h1[MM * CI];
__device__ float d_aggr[MM * CI];
__device__ int   d_cnt[MM];
__device__ __align__(16) float d_Wt0[P2N * 1024 * 2];   // p-paired layout [p2][j][2]
__device__ __align__(16) float d_Wt1[P2N * 1024 * 2];
__device__ __align__(16) float d_Wt2[P2N * 512 * 2];
__device__ float d_A[EMB * 3];
__device__ float d_cc[EMB];
__device__ float d_K2[BB * TT * EMB];
__device__ float d_V2[BB * TT * EMB];
__device__ float d_U[BB * NH * TT * 3];
__device__ float d_s0[BB * NH * TT];
__device__ float d_OV[BB * NH * TT * EMB];

// ---------------- packed f32x2 helpers ----------------
__device__ __forceinline__ void fma2(ull& d, ull a, ull b) {
    asm("fma.rn.f32x2 %0, %1, %2, %0;" : "+l"(d) : "l"(a), "l"(b));
}
__device__ __forceinline__ float red2(ull v) {
    float lo, hi;
    asm("mov.b64 {%0, %1}, %2;" : "=f"(lo), "=f"(hi) : "l"(v));
    return lo + hi;
}

// ---------------- setup kernels ----------------

// blocks 0..63: K2/V2 with inline positional encoding; block 64: A = wq@Wq_w, cc = bq + wq@Wq_b
__global__ void s2f_kernel(const float* __restrict__ gt,
                           const float* __restrict__ Wk_w, const float* __restrict__ Wk_b,
                           const float* __restrict__ Wv_w, const float* __restrict__ Wv_b,
                           const float* __restrict__ ipw, const float* __restrict__ ipb,
                           const float* __restrict__ Wq_w, const float* __restrict__ Wq_b) {
    if (blockIdx.x == BB * TT) {
        int t = threadIdx.x;
        for (int idx = t; idx < EMB * 3; idx += blockDim.x) {
            int j = idx / 3, p = idx % 3;
            float s = 0.f;
            for (int i = 0; i < EMB; i++) s += ipw[j * EMB + i] * Wq_w[i * 3 + p];
            d_A[idx] = s;
        }
        for (int j = t; j < EMB; j += blockDim.x) {
            float s = ipb[j];
            for (int i = 0; i < EMB; i++) s += ipw[j * EMB + i] * Wq_b[i];
            d_cc[j] = s;
        }
        return;
    }
    __shared__ float Kt[EMB], Vt[EMB];
    int bt = blockIdx.x;            // b*TT + t
    int tloc = bt % TT;
    int j = threadIdx.x;            // 0..63
    const float* g  = gt + (size_t)bt * GDIM;
    const float* wk = Wk_w + (size_t)j * GDIM;
    const float* wv = Wv_w + (size_t)j * GDIM;
    float sk = 0.f, sv = 0.f;
    for (int i = 0; i < GDIM; i += 4) {
        float4 gv = *(const float4*)(g + i);
        float4 k4 = *(const float4*)(wk + i);
        float4 v4 = *(const float4*)(wv + i);
        sk += gv.x * k4.x + gv.y * k4.y + gv.z * k4.z + gv.w * k4.w;
        sv += gv.x * v4.x + gv.y * v4.y + gv.z * v4.z + gv.w * v4.w;
    }
    // inline positional encoding
    int i2 = j & ~1;
    float div = expf(-(float)i2 * (9.210340371976184f / (float)EMB));
    float ang = (float)tloc * div;
    float pe = (j & 1) ? cosf(ang) : sinf(ang);
    Kt[j] = sk + Wk_b[j] + pe;
    Vt[j] = sv + Wv_b[j] + pe;
    __syncthreads();
    const float* wkr = ipw + (size_t)(EMB + j) * EMB;
    const float* wvr = ipw + (size_t)(2 * EMB + j) * EMB;
    float s2k = ipb[EMB + j], s2v = ipb[2 * EMB + j];
    for (int i = 0; i < EMB; i++) { s2k += Kt[i] * wkr[i]; s2v += Vt[i] * wvr[i]; }
    d_K2[bt * EMB + j] = s2k;
    d_V2[bt * EMB + j] = s2v;
}

// Per graph: U[h,t,3], s0[h,t], OV[(h,t), j] = out_w-folded V
__global__ void s3_kernel(const float* __restrict__ out_w) {
    int b = blockIdx.x;
    int t = threadIdx.x;
    for (int idx = t; idx < NH * TT * 3; idx += blockDim.x) {
        int p = idx % 3; int ht = idx / 3; int h = ht / TT, tt = ht % TT;
        float s = 0.f;
        for (int d = 0; d < HD; d++)
            s += d_A[(h * HD + d) * 3 + p] * d_K2[(b * TT + tt) * EMB + h * HD + d];
        d_U[b * NH * TT * 3 + idx] = 0.25f * s;
    }
    for (int idx = t; idx < NH * TT; idx += blockDim.x) {
        int h = idx / TT, tt = idx % TT;
        float s = 0.f;
        for (int d = 0; d < HD; d++)
            s += d_cc[h * HD + d] * d_K2[(b * TT + tt) * EMB + h * HD + d];
        d_s0[b * NH * TT + idx] = 0.25f * s;
    }
    for (int idx = t; idx < NH * TT * EMB; idx += blockDim.x) {
        int j = idx % EMB; int ht = idx / EMB; int h = ht / TT, tt = ht % TT;
        float s = 0.f;
        for (int d = 0; d < HD; d++)
            s += out_w[j * EMB + h * HD + d] * d_V2[(b * TT + tt) * EMB + h * HD + d];
        d_OV[b * NH * TT * EMB + idx] = s;
    }
}

// Build p-paired, transposed weights for all 3 layers in one launch.
__global__ void trans_all_kernel(const float* __restrict__ nw0, const float* __restrict__ nw1,
                                 const float* __restrict__ nw2) {
    int idx = blockIdx.x * blockDim.x + threadIdx.x;
    const float* nw; float* wt; int J; int local;
    if (idx < P2N * 1024)            { nw = nw0; wt = d_Wt0; J = 1024; local = idx; }
    else if (idx < 2 * P2N * 1024)   { nw = nw1; wt = d_Wt1; J = 1024; local = idx - P2N * 1024; }
    else if (idx < 2 * P2N * 1024 + P2N * 512) { nw = nw2; wt = d_Wt2; J = 512; local = idx - 2 * P2N * 1024; }
    else return;
    int p2 = local / J, j = local - p2 * J;
    float lo = nw[j * PDIM + 2 * p2];
    float hi = (2 * p2 + 1 < PDIM) ? nw[j * PDIM + 2 * p2 + 1] : 0.f;
    wt[local * 2]     = lo;
    wt[local * 2 + 1] = hi;
}

// ---------------- stage A: knn interpolate + concat (+ zero cnt & aggr) ----------------
__global__ void knn_kernel(const float* __restrict__ x, const float* __restrict__ pos,
                           const float* __restrict__ x_skip, const float* __restrict__ pos_skip) {
    __shared__ float cx[NPG], cy[NPG], cz[NPG], cn2[NPG];
    int m = blockIdx.x * blockDim.x + threadIdx.x;
    int b = m / MPG;
    const float* cp = pos + (size_t)b * NPG * 3;
    for (int j = threadIdx.x; j < NPG; j += blockDim.x) {
        float X = cp[j * 3], Y = cp[j * 3 + 1], Z = cp[j * 3 + 2];
        cx[j] = X; cy[j] = Y; cz[j] = Z; cn2[j] = X * X + Y * Y + Z * Z;
    }
    __syncthreads();
    // fold in: zero degree counter + layer-0 aggregation buffer
    d_cnt[m] = 0;
    float4 z4 = make_float4(0.f, 0.f, 0.f, 0.f);
    #pragma unroll
    for (int q = 0; q < CI / 4; q++) ((float4*)(d_aggr + (size_t)m * CI))[q] = z4;

    float px = pos_skip[m * 3], py = pos_skip[m * 3 + 1], pz = pos_skip[m * 3 + 2];
    float ps2 = px * px + py * py + pz * pz;
    float b0 = 1e30f, b1 = 1e30f, b2 = 1e30f;
    int i0 = 0, i1 = 0, i2 = 0;
    for (int j = 0; j < NPG; j++) {
        float d = ps2 + cn2[j] - 2.f * (px * cx[j] + py * cy[j] + pz * cz[j]);
        if (d < b2) {
            if (d < b1) {
                b2 = b1; i2 = i1;
                if (d < b0) { b1 = b0; i1 = i0; b0 = d; i0 = j; }
                else        { b1 = d;  i1 = j; }
            } else { b2 = d; i2 = j; }
        }
    }
    float w0 = 1.f / fmaxf(b0, 1e-16f);
    float w1 = 1.f / fmaxf(b1, 1e-16f);
    float w2 = 1.f / fmaxf(b2, 1e-16f);
    float inv = 1.f / (w0 + w1 + w2);
    const float* x0 = x + (size_t)(b * NPG + i0) * FIN;
    const float* x1 = x + (size_t)(b * NPG + i1) * FIN;
    const float* x2 = x + (size_t)(b * NPG + i2) * FIN;
    const float* xs = x_skip + (size_t)m * FIN;
    float* h = d_h0 + (size_t)m * CI;
    #pragma unroll
    for (int f = 0; f < FIN; f++) {
        h[f]       = (w0 * x0[f] + w1 * x1[f] + w2 * x2[f]) * inv;
        h[FIN + f] = xs[f];
    }
}

// ---------------- degree ----------------
__global__ void deg_kernel(const int* __restrict__ ei) {
    int e = blockIdx.x * blockDim.x + threadIdx.x;
    if (e < EE) atomicAdd(&d_cnt[ei[EE + e]], 1);
}

// ---------------- stage B: per-edge attention -> pseudo [E,67] ----------------
__global__ void attn_kernel(const int* __restrict__ ei, const float* __restrict__ pos_skip,
                            const float* __restrict__ out_b) {
    __shared__ float4 sOV4[NH * TT * EMB / 4];
    __shared__ float sU[NH * TT * 3], sS0[NH * TT], sOB[EMB];
    int e = blockIdx.x * blockDim.x + threadIdx.x;
    int b = blockIdx.x / (EPG / 256);
    float* sOV = (float*)sOV4;
    for (int i = threadIdx.x; i < NH * TT * EMB; i += 256) sOV[i] = d_OV[b * NH * TT * EMB + i];
    for (int i = threadIdx.x; i < NH * TT * 3;  i += 256) sU[i]  = d_U[b * NH * TT * 3 + i];
    for (int i = threadIdx.x; i < NH * TT;      i += 256) sS0[i] = d_s0[b * NH * TT + i];
    for (int i = threadIdx.x; i < EMB;          i += 256) sOB[i] = out_b[i];
    __syncthreads();
    int s = ei[e], d = ei[EE + e];
    float sx = pos_skip[s * 3], sy = pos_skip[s * 3 + 1], sz = pos_skip[s * 3 + 2];
    float dx = pos_skip[d * 3], dy = pos_skip[d * 3 + 1], dz = pos_skip[d * 3 + 2];
    float epx = 0.5f * (dx + sx), epy = 0.5f * (dy + sy), epz = 0.5f * (dz + sz);
    float4 o4[EMB / 4];
    #pragma unroll
    for (int q = 0; q < EMB / 4; q++) {
        o4[q].x = sOB[4 * q]; o4[q].y = sOB[4 * q + 1];
        o4[q].z = sOB[4 * q + 2]; o4[q].w = sOB[4 * q + 3];
    }
    #pragma unroll
    for (int h = 0; h < NH; h++) {
        float sc[TT];
        float mx = -1e30f;
        #pragma unroll
        for (int t = 0; t < TT; t++) {
            int ht = h * TT + t;
            sc[t] = sS0[ht] + epx * sU[ht * 3] + epy * sU[ht * 3 + 1] + epz * sU[ht * 3 + 2];
            mx = fmaxf(mx, sc[t]);
        }
        float se = 0.f;
        #pragma unroll
        for (int t = 0; t < TT; t++) { sc[t] = __expf(sc[t] - mx); se += sc[t]; }
        float inv = 1.f / se;
        #pragma unroll
        for (int t = 0; t < TT; t++) {
            float a = sc[t] * inv;
            const float4* row = sOV4 + (h * TT + t) * (EMB / 4);
            #pragma unroll
            for (int q = 0; q < EMB / 4; q++) {
                float4 v = row[q];
                o4[q].x += a * v.x; o4[q].y += a * v.y;
                o4[q].z += a * v.z; o4[q].w += a * v.w;
            }
        }
    }
    float* pd = d_pseudo + (size_t)e * PDIM;
    pd[0] = dx - sx; pd[1] = dy - sy; pd[2] = dz - sz;
    #pragma unroll
    for (int q = 0; q < EMB / 4; q++) {
        pd[3 + 4 * q] = o4[q].x; pd[4 + 4 * q] = o4[q].y;
        pd[5 + 4 * q] = o4[q].z; pd[6 + 4 * q] = o4[q].w;
    }
}

// ---------------- stage C: fused edge MLP (packed f32x2, smem-staged weights) ----------------
template <int CO>
__global__ void __launch_bounds__(CO * 8)
edge_kernel(int layer, const int* __restrict__ ei, const float* __restrict__ nb) {
    constexpr int NT = CO * 8;
    constexpr int BE = 64;    // edges per block
    constexpr int GE = 8;     // edges per thread
    constexpr int J  = CI * CO;
    constexpr int WS = P2N * 4 * CO;                 // ulls per ic-block weight slice
    extern __shared__ __align__(16) ull ws[];        // dynamic: WS ulls
    __shared__ __align__(16) float ps_s[BE * 70];    // p-padded rows (67..69 zero)
    __shared__ float hs_s[BE * 33];
    __shared__ float nb_s[J];
    __shared__ int   dst_s[BE];

    const ull* WtU = (const ull*)((layer == 0) ? d_Wt0 : (layer == 1) ? d_Wt1 : d_Wt2);
    const float* hin = (layer == 1) ? d_h1 : d_h0;

    int e0 = blockIdx.x * BE;
    for (int idx = threadIdx.x; idx < BE * 70; idx += NT) {
        int el = idx / 70, p = idx - el * 70;
        ps_s[idx] = (p < PDIM) ? d_pseudo[(size_t)(e0 + el) * PDIM + p] : 0.f;
    }
    for (int idx = threadIdx.x; idx < BE * CI; idx += NT) {
        int el = idx >> 5, i = idx & 31;
        hs_s[el * 33 + i] = hin[(size_t)ei[e0 + el] * CI + i];
    }
    for (int idx = threadIdx.x; idx < BE; idx += NT) dst_s[idx] = ei[EE + e0 + idx];
    for (int idx = threadIdx.x; idx < J; idx += NT) nb_s[idx] = nb[idx];

    int o = threadIdx.x % CO;
    int g = threadIdx.x / CO;
    const ull* psg2 = (const ull*)(ps_s + g * GE * 70);   // row stride 35 ulls
    const float* hsg = hs_s + g * GE * 33;
    float msg[GE];
    #pragma unroll
    for (int k = 0; k < GE; k++) msg[k] = 0.f;

    __syncthreads();

    #pragma unroll 1
    for (int b4 = 0; b4 < CI / 4; b4++) {
        if (b4) __syncthreads();
        // stage this ic-block's weight slice: ws[p2*4CO + r] = Wt[p2*J + b4*4CO + r]
        for (int idx = threadIdx.x; idx < WS; idx += NT) {
            int p2 = idx / (4 * CO), r = idx - p2 * (4 * CO);
            ws[idx] = WtU[(size_t)p2 * J + b4 * 4 * CO + r];
        }
        __syncthreads();

        ull z2[4][GE];
        #pragma unroll
        for (int i = 0; i < 4; i++)
            #pragma unroll
            for (int k = 0; k < GE; k++) z2[i][k] = 0ull;

        const ull* wp = ws + o;
        #pragma unroll 2
        for (int p2 = 0; p2 < P2N; p2++) {
            ull w2[4];
            #pragma unroll
            for (int i = 0; i < 4; i++) w2[i] = wp[p2 * 4 * CO + i * CO];
            ull a2[GE];
            #pragma unroll
            for (int k = 0; k < GE; k++) a2[k] = psg2[k * 35 + p2];
            #pragma unroll
            for (int i = 0; i < 4; i++)
                #pragma unroll
                for (int k = 0; k < GE; k++) fma2(z2[i][k], a2[k], w2[i]);
        }
        #pragma unroll
        for (int i = 0; i < 4; i++) {
            float nbv = nb_s[(b4 * 4 + i) * CO + o];
            #pragma unroll
            for (int k = 0; k < GE; k++) {
                float z = red2(z2[i][k]) + nbv;
                msg[k] = fmaf(hsg[k * 33 + b4 * 4 + i], fmaxf(z, 0.f), msg[k]);
            }
        }
    }
    #pragma unroll
    for (int k = 0; k < GE; k++)
        atomicAdd(&d_aggr[(size_t)dst_s[g * GE + k] * CO + o], msg[k]);
}

// node update: h_out = relu(aggr/cnt + h_in @ root + bias); also re-zeroes aggr for next layer
template <int CO>
__global__ void node_kernel(int layer, const float* __restrict__ root,
                            const float* __restrict__ bias, float* __restrict__ finalout,
                            int out_size) {
    __shared__ float4 root4[CI * CO / 4];
    __shared__ float  bias_s[CO];
    for (int i = threadIdx.x; i < CI * CO / 4; i += blockDim.x) root4[i] = ((const float4*)root)[i];
    for (int i = threadIdx.x; i < CO; i += blockDim.x) bias_s[i] = bias[i];
    __syncthreads();

    const float* hin = (layer == 1) ? d_h1 : d_h0;
    int v = blockIdx.x * blockDim.x + threadIdx.x;
    float inv = 1.f / (float)max(d_cnt[v], 1);

    float4 acc[CO / 4];
    #pragma unroll
    for (int q = 0; q < CO / 4; q++) {
        float4 ag = ((const float4*)(d_aggr + (size_t)v * CO))[q];
        acc[q].x = bias_s[4 * q]     + ag.x * inv;
        acc[q].y = bias_s[4 * q + 1] + ag.y * inv;
        acc[q].z = bias_s[4 * q + 2] + ag.z * inv;
        acc[q].w = bias_s[4 * q + 3] + ag.w * inv;
    }
    if (layer < 2) {
        // re-zero the aggregation buffer for the next layer (each v owned by one thread)
        float4 z4 = make_float4(0.f, 0.f, 0.f, 0.f);
        #pragma unroll
        for (int q = 0; q < CI / 4; q++) ((float4*)(d_aggr + (size_t)v * CI))[q] = z4;
    }
    float hv[CI];
    #pragma unroll
    for (int q = 0; q < CI / 4; q++) {
        float4 t = ((const float4*)(hin + (size_t)v * CI))[q];
        hv[4 * q] = t.x; hv[4 * q + 1] = t.y; hv[4 * q + 2] = t.z; hv[4 * q + 3] = t.w;
    }
    #pragma unroll
    for (int i = 0; i < CI; i++) {
        #pragma unroll
        for (int q = 0; q < CO / 4; q++) {
            float4 r = root4[i * (CO / 4) + q];
            acc[q].x = fmaf(hv[i], r.x, acc[q].x);
            acc[q].y = fmaf(hv[i], r.y, acc[q].y);
            acc[q].z = fmaf(hv[i], r.z, acc[q].z);
            acc[q].w = fmaf(hv[i], r.w, acc[q].w);
        }
    }
    float* hout = (layer == 0) ? d_h1 : (layer == 1) ? d_h0 : finalout;
    #pragma unroll
    for (int q = 0; q < CO / 4; q++) {
        float4 r;
        r.x = fmaxf(acc[q].x, 0.f); r.y = fmaxf(acc[q].y, 0.f);
        r.z = fmaxf(acc[q].z, 0.f); r.w = fmaxf(acc[q].w, 0.f);
        if (layer == 2) {
            int ofs = v * CO + 4 * q;
            if (ofs + 4 <= out_size) ((float4*)(hout + ofs))[0] = r;
        } else {
            ((float4*)(hout + (size_t)v * CO))[q] = r;
        }
    }
}

// remaining reference outputs (pos_skip, batch_skip) if the harness expects them
__global__ void tail_kernel(const float* __restrict__ pos_skip, const int* __restrict__ batch_skip,
                            float* __restrict__ out, int out_size) {
    int i = blockIdx.x * blockDim.x + threadIdx.x;
    int base = MM * 16;
    if (i < MM * 3 && base + i < out_size) out[base + i] = pos_skip[i];
    int base2 = base + MM * 3;
    if (i < MM && base2 + i < out_size) out[base2 + i] = (float)batch_skip[i];
}

// ---------------- launch ----------------
extern "C" void kernel_launch(void* const* d_in, const int* in_sizes, int n_in,
                              void* d_out, int out_size) {
    const float* x        = (const float*)d_in[0];
    const float* pos      = (const float*)d_in[1];
    const float* x_skip   = (const float*)d_in[3];
    const float* pos_skip = (const float*)d_in[4];
    const int*   batch_sk = (const int*)  d_in[5];
    const int*   ei       = (const int*)  d_in[6];
    const float* gt       = (const float*)d_in[7];
    const float* Wq_w = (const float*)d_in[8];   const float* Wq_b = (const float*)d_in[9];
    const float* Wk_w = (const float*)d_in[10];  const float* Wk_b = (const float*)d_in[11];
    const float* Wv_w = (const float*)d_in[12];  const float* Wv_b = (const float*)d_in[13];
    const float* ipw  = (const float*)d_in[14];  const float* ipb  = (const float*)d_in[15];
    const float* ow   = (const float*)d_in[16];  const float* ob   = (const float*)d_in[17];
    const float* nw0 = (const float*)d_in[18]; const float* nb0 = (const float*)d_in[19];
    const float* rt0 = (const float*)d_in[20]; const float* bs0 = (const float*)d_in[21];
    const float* rt1 = (const float*)d_in[24]; const float* bs1 = (const float*)d_in[25];
    const float* nw1 = (const float*)d_in[22]; const float* nb1 = (const float*)d_in[23];
    const float* nw2 = (const float*)d_in[26]; const float* nb2 = (const float*)d_in[27];
    const float* rt2 = (const float*)d_in[28]; const float* bs2 = (const float*)d_in[29];
    float* out = (float*)d_out;

    // opt-in dynamic smem (static 30.7KB + dynamic slice > 48KB default)
    constexpr int WS32 = P2N * 4 * 32 * (int)sizeof(ull);  // 34816 B
    constexpr int WS16 = P2N * 4 * 16 * (int)sizeof(ull);  // 17408 B
    cudaFuncSetAttribute(edge_kernel<32>, cudaFuncAttributeMaxDynamicSharedMemorySize, WS32);
    cudaFuncSetAttribute(edge_kernel<16>, cudaFuncAttributeMaxDynamicSharedMemorySize, WS16);

    // launches 1..5 (setup) — edge_kernel<32> is launch #6 = the ncu -s 5 capture slot
    s2f_kernel<<<BB * TT + 1, EMB>>>(gt, Wk_w, Wk_b, Wv_w, Wv_b, ipw, ipb, Wq_w, Wq_b);
    s3_kernel<<<BB, 256>>>(ow);
    trans_all_kernel<<<(2 * P2N * 1024 + P2N * 512 + 255) / 256, 256>>>(nw0, nw1, nw2);
    knn_kernel<<<MM / 256, 256>>>(x, pos, x_skip, pos_skip);   // also zeroes cnt + aggr
    attn_kernel<<<EE / 256, 256>>>(ei, pos_skip, ob);

    // stage C: 3 NNConv layers
    edge_kernel<32><<<EE / 64, 256, WS32>>>(0, ei, nb0);       // launch #6 (profiled)
    deg_kernel<<<EE / 256, 256>>>(ei);
    node_kernel<32><<<MM / 256, 256>>>(0, rt0, bs0, nullptr, 0);   // zeroes aggr for L1
    edge_kernel<32><<<EE / 64, 256, WS32>>>(1, ei, nb1);
    node_kernel<32><<<MM / 256, 256>>>(1, rt1, bs1, nullptr, 0);   // zeroes aggr for L2
    edge_kernel<16><<<EE / 64, 128, WS16>>>(2, ei, nb2);
    node_kernel<16><<<MM / 256, 256>>>(2, rt2, bs2, out, out_size);

    // remaining tuple outputs if expected
    tail_kernel<<<(MM * 3 + 255) / 256, 256>>>(pos_skip, batch_sk, out, out_size);
}

// round 10
// speedup vs baseline: 1.0615x; 1.0615x over previous
#include <cuda_runtime.h>

// ---------------- problem constants ----------------
#define BB   4
#define NPG  2048        // coarse nodes per graph
#define MM   65536       // skip nodes
#define MPG  16384
#define EE   131072      // edges
#define EPG  32768
#define TT   16          // tokens per graph
#define FIN  16
#define GDIM 1024
#define EMB  64
#define NH   4
#define HD   16
#define CI   32
#define PDIM 67          // 3 + 64
#define PSTR 68          // padded pseudo row stride (16B aligned, 34 pairs)
#define P2N  34          // p-pairs

typedef unsigned long long ull;

// ---------------- device scratch (no cudaMalloc allowed) ----------------
__device__ __align__(16) float d_pseudo[EE * PSTR];   // 35.6 MB, padded rows
__device__ float d_h0[MM * CI];
__device__ float d_h1[MM * CI];
__device__ float d_aggr[MM * CI];
__device__ int   d_cnt[MM];
// weight layout per layer: ull index ((p2*8 + b4)*CO + o)*4 + i  -> float pair (2*p2, 2*p2+1)
__device__ __align__(16) float d_Wt0[P2N * 1024 * 2];
__device__ __align__(16) float d_Wt1[P2N * 1024 * 2];
__device__ __align__(16) float d_Wt2[P2N * 512 * 2];
__device__ float d_A[EMB * 3];
__device__ float d_cc[EMB];
__device__ float d_K2[BB * TT * EMB];
__device__ float d_V2[BB * TT * EMB];
__device__ float d_U[BB * NH * TT * 3];
__device__ float d_s0[BB * NH * TT];
__device__ float d_OV[BB * NH * TT * EMB];

// ---------------- packed f32x2 helpers ----------------
__device__ __forceinline__ void fma2(ull& d, ull a, ull b) {
    asm("fma.rn.f32x2 %0, %1, %2, %0;" : "+l"(d) : "l"(a), "l"(b));
}
__device__ __forceinline__ float red2(ull v) {
    float lo, hi;
    asm("mov.b64 {%0, %1}, %2;" : "=f"(lo), "=f"(hi) : "l"(v));
    return lo + hi;
}

// ---------------- setup kernel: K2/V2 tokens + A/cc + weight re-layout, one launch ----------------
#define TRW0 (P2N * 1024)          // ull count, layer 0
#define TRW1 (P2N * 1024)
#define TRW2 (P2N * 512)
#define TRBLK ((TRW0 + TRW1 + TRW2) / 256)   // 340 blocks

__global__ void setup_kernel(const float* __restrict__ gt,
                             const float* __restrict__ Wk_w, const float* __restrict__ Wk_b,
                             const float* __restrict__ Wv_w, const float* __restrict__ Wv_b,
                             const float* __restrict__ ipw, const float* __restrict__ ipb,
                             const float* __restrict__ Wq_w, const float* __restrict__ Wq_b,
                             const float* __restrict__ nw0, const float* __restrict__ nw1,
                             const float* __restrict__ nw2) {
    int bid = blockIdx.x;
    if (bid < BB * TT) {
        // token projections, 4-way split over GDIM
        __shared__ float pK[4][EMB], pV[4][EMB];
        __shared__ float Kt[EMB], Vt[EMB];
        int bt = bid, tloc = bt % TT;
        int q = threadIdx.x >> 6, j = threadIdx.x & 63;
        const float* g  = gt + (size_t)bt * GDIM + q * 256;
        const float* wk = Wk_w + (size_t)j * GDIM + q * 256;
        const float* wv = Wv_w + (size_t)j * GDIM + q * 256;
        float sk = 0.f, sv = 0.f;
        for (int i = 0; i < 256; i += 4) {
            float4 gv = *(const float4*)(g + i);
            float4 k4 = *(const float4*)(wk + i);
            float4 v4 = *(const float4*)(wv + i);
            sk += gv.x * k4.x + gv.y * k4.y + gv.z * k4.z + gv.w * k4.w;
            sv += gv.x * v4.x + gv.y * v4.y + gv.z * v4.z + gv.w * v4.w;
        }
        pK[q][j] = sk; pV[q][j] = sv;
        __syncthreads();
        if (q == 0) {
            int i2 = j & ~1;
            float div = expf(-(float)i2 * (9.210340371976184f / (float)EMB));
            float ang = (float)tloc * div;
            float pe = (j & 1) ? cosf(ang) : sinf(ang);
            Kt[j] = pK[0][j] + pK[1][j] + pK[2][j] + pK[3][j] + Wk_b[j] + pe;
            Vt[j] = pV[0][j] + pV[1][j] + pV[2][j] + pV[3][j] + Wv_b[j] + pe;
        }
        __syncthreads();
        if (q == 0) {
            const float* wkr = ipw + (size_t)(EMB + j) * EMB;
            const float* wvr = ipw + (size_t)(2 * EMB + j) * EMB;
            float s2k = ipb[EMB + j], s2v = ipb[2 * EMB + j];
            for (int i = 0; i < EMB; i++) { s2k += Kt[i] * wkr[i]; s2v += Vt[i] * wvr[i]; }
            d_K2[bt * EMB + j] = s2k;
            d_V2[bt * EMB + j] = s2v;
        }
        return;
    }
    if (bid == BB * TT) {
        // A = wq @ Wq_w, cc = bq + wq @ Wq_b
        int t = threadIdx.x;
        for (int idx = t; idx < EMB * 3; idx += blockDim.x) {
            int j = idx / 3, p = idx % 3;
            float s = 0.f;
            for (int i = 0; i < EMB; i++) s += ipw[j * EMB + i] * Wq_w[i * 3 + p];
            d_A[idx] = s;
        }
        for (int j = t; j < EMB; j += blockDim.x) {
            float s = ipb[j];
            for (int i = 0; i < EMB; i++) s += ipw[j * EMB + i] * Wq_b[i];
            d_cc[j] = s;
        }
        return;
    }
    // weight re-layout
    int u = (bid - (BB * TT + 1)) * 256 + threadIdx.x;
    const float* nw; float* wt; int CO;
    if (u < TRW0)              { nw = nw0; wt = d_Wt0; CO = 32; }
    else if (u < TRW0 + TRW1)  { nw = nw1; wt = d_Wt1; CO = 32; u -= TRW0; }
    else                       { nw = nw2; wt = d_Wt2; CO = 16; u -= TRW0 + TRW1; }
    int i  = u & 3;
    int o  = (u >> 2) % CO;
    int b4 = ((u >> 2) / CO) & 7;
    int p2 = u / (32 * CO);
    int j  = (b4 * 4 + i) * CO + o;
    float lo = nw[j * PDIM + 2 * p2];
    float hi = (2 * p2 + 1 < PDIM) ? nw[j * PDIM + 2 * p2 + 1] : 0.f;
    wt[(size_t)u * 2]     = lo;
    wt[(size_t)u * 2 + 1] = hi;
}

// ---------------- mid kernel: s3 (blocks 0..3) + knn (blocks 4..) ----------------
__global__ void mid_kernel(const float* __restrict__ x, const float* __restrict__ pos,
                           const float* __restrict__ x_skip, const float* __restrict__ pos_skip,
                           const float* __restrict__ out_w) {
    __shared__ __align__(16) float4 sh4[NPG];   // {x, y, z, -0.5*|c|^2}
    int bid = blockIdx.x;
    if (bid < BB) {
        int b = bid, t = threadIdx.x;
        for (int idx = t; idx < NH * TT * 3; idx += blockDim.x) {
            int p = idx % 3; int ht = idx / 3; int h = ht / TT, tt = ht % TT;
            float s = 0.f;
            for (int d = 0; d < HD; d++)
                s += d_A[(h * HD + d) * 3 + p] * d_K2[(b * TT + tt) * EMB + h * HD + d];
            d_U[b * NH * TT * 3 + idx] = 0.25f * s;
        }
        for (int idx = t; idx < NH * TT; idx += blockDim.x) {
            int h = idx / TT, tt = idx % TT;
            float s = 0.f;
            for (int d = 0; d < HD; d++)
                s += d_cc[h * HD + d] * d_K2[(b * TT + tt) * EMB + h * HD + d];
            d_s0[b * NH * TT + idx] = 0.25f * s;
        }
        for (int idx = t; idx < NH * TT * EMB; idx += blockDim.x) {
            int j = idx % EMB; int ht = idx / EMB; int h = ht / TT, tt = ht % TT;
            float s = 0.f;
            for (int d = 0; d < HD; d++)
                s += out_w[j * EMB + h * HD + d] * d_V2[(b * TT + tt) * EMB + h * HD + d];
            d_OV[b * NH * TT * EMB + idx] = s;
        }
        return;
    }
    // ---- knn part: 128 threads/block, one skip node per thread ----
    int m = (bid - BB) * 128 + threadIdx.x;
    int b = m / MPG;
    const float* cp = pos + (size_t)b * NPG * 3;
    for (int j = threadIdx.x; j < NPG; j += 128) {
        float X = cp[j * 3], Y = cp[j * 3 + 1], Z = cp[j * 3 + 2];
        sh4[j] = make_float4(X, Y, Z, -0.5f * (X * X + Y * Y + Z * Z));
    }
    __syncthreads();

    // fold in: zero degree counter + layer-0 aggregation buffer
    d_cnt[m] = 0;
    float4 z4 = make_float4(0.f, 0.f, 0.f, 0.f);
    #pragma unroll
    for (int q = 0; q < CI / 4; q++) ((float4*)(d_aggr + (size_t)m * CI))[q] = z4;

    float px = pos_skip[m * 3], py = pos_skip[m * 3 + 1], pz = pos_skip[m * 3 + 2];
    float ps2 = px * px + py * py + pz * pz;
    // maximize s = dot - 0.5*|c|^2  (equiv. minimize squared distance)
    float b0 = -1e30f, b1 = -1e30f, b2 = -1e30f;
    int i0 = 0, i1 = 0, i2 = 0;
    #pragma unroll 4
    for (int j = 0; j < NPG; j++) {
        float4 c = sh4[j];
        float s = fmaf(px, c.x, fmaf(py, c.y, fmaf(pz, c.z, c.w)));
        if (s > b2) {
            if (s > b1) {
                b2 = b1; i2 = i1;
                if (s > b0) { b1 = b0; i1 = i0; b0 = s; i0 = j; }
                else        { b1 = s;  i1 = j; }
            } else { b2 = s; i2 = j; }
        }
    }
    float d0 = fmaf(-2.f, b0, ps2);
    float d1 = fmaf(-2.f, b1, ps2);
    float d2 = fmaf(-2.f, b2, ps2);
    float w0 = 1.f / fmaxf(d0, 1e-16f);
    float w1 = 1.f / fmaxf(d1, 1e-16f);
    float w2 = 1.f / fmaxf(d2, 1e-16f);
    float inv = 1.f / (w0 + w1 + w2);
    const float* x0 = x + (size_t)(b * NPG + i0) * FIN;
    const float* x1 = x + (size_t)(b * NPG + i1) * FIN;
    const float* x2 = x + (size_t)(b * NPG + i2) * FIN;
    const float* xs = x_skip + (size_t)m * FIN;
    float* h = d_h0 + (size_t)m * CI;
    #pragma unroll
    for (int f = 0; f < FIN; f++) {
        h[f]       = (w0 * x0[f] + w1 * x1[f] + w2 * x2[f]) * inv;
        h[FIN + f] = xs[f];
    }
}

// ---------------- degree ----------------
__global__ void deg_kernel(const int* __restrict__ ei) {
    int e = blockIdx.x * blockDim.x + threadIdx.x;
    if (e < EE) atomicAdd(&d_cnt[ei[EE + e]], 1);
}

// ---------------- stage B: per-edge attention -> pseudo [E,68(padded)] ----------------
__global__ void attn_kernel(const int* __restrict__ ei, const float* __restrict__ pos_skip,
                            const float* __restrict__ out_b) {
    __shared__ float4 sOV4[NH * TT * EMB / 4];
    __shared__ float sU[NH * TT * 3], sS0[NH * TT], sOB[EMB];
    int e = blockIdx.x * blockDim.x + threadIdx.x;
    int b = blockIdx.x / (EPG / 256);
    float* sOV = (float*)sOV4;
    for (int i = threadIdx.x; i < NH * TT * EMB; i += 256) sOV[i] = d_OV[b * NH * TT * EMB + i];
    for (int i = threadIdx.x; i < NH * TT * 3;  i += 256) sU[i]  = d_U[b * NH * TT * 3 + i];
    for (int i = threadIdx.x; i < NH * TT;      i += 256) sS0[i] = d_s0[b * NH * TT + i];
    for (int i = threadIdx.x; i < EMB;          i += 256) sOB[i] = out_b[i];
    __syncthreads();
    int s = ei[e], d = ei[EE + e];
    float sx = pos_skip[s * 3], sy = pos_skip[s * 3 + 1], sz = pos_skip[s * 3 + 2];
    float dx = pos_skip[d * 3], dy = pos_skip[d * 3 + 1], dz = pos_skip[d * 3 + 2];
    float epx = 0.5f * (dx + sx), epy = 0.5f * (dy + sy), epz = 0.5f * (dz + sz);
    float4 o4[EMB / 4];
    #pragma unroll
    for (int q = 0; q < EMB / 4; q++) {
        o4[q].x = sOB[4 * q]; o4[q].y = sOB[4 * q + 1];
        o4[q].z = sOB[4 * q + 2]; o4[q].w = sOB[4 * q + 3];
    }
    #pragma unroll
    for (int h = 0; h < NH; h++) {
        float sc[TT];
        float mx = -1e30f;
        #pragma unroll
        for (int t = 0; t < TT; t++) {
            int ht = h * TT + t;
            sc[t] = sS0[ht] + epx * sU[ht * 3] + epy * sU[ht * 3 + 1] + epz * sU[ht * 3 + 2];
            mx = fmaxf(mx, sc[t]);
        }
        float se = 0.f;
        #pragma unroll
        for (int t = 0; t < TT; t++) { sc[t] = __expf(sc[t] - mx); se += sc[t]; }
        float inv = 1.f / se;
        #pragma unroll
        for (int t = 0; t < TT; t++) {
            float a = sc[t] * inv;
            const float4* row = sOV4 + (h * TT + t) * (EMB / 4);
            #pragma unroll
            for (int q = 0; q < EMB / 4; q++) {
                float4 v = row[q];
                o4[q].x += a * v.x; o4[q].y += a * v.y;
                o4[q].z += a * v.z; o4[q].w += a * v.w;
            }
        }
    }
    float* pd = d_pseudo + (size_t)e * PSTR;
    pd[0] = dx - sx; pd[1] = dy - sy; pd[2] = dz - sz;
    #pragma unroll
    for (int q = 0; q < EMB / 4; q++) {
        pd[3 + 4 * q] = o4[q].x; pd[4 + 4 * q] = o4[q].y;
        pd[5 + 4 * q] = o4[q].z; pd[6 + 4 * q] = o4[q].w;
    }
    pd[67] = 0.f;   // pair padding
}

// ---------------- stage C: fused edge MLP (packed f32x2) + message + scatter ----------------
template <int CO>
__global__ void __launch_bounds__(CO * 8)
edge_kernel(int layer, const int* __restrict__ ei, const float* __restrict__ nb) {
    constexpr int NT = CO * 8;
    constexpr int BE = 64;    // edges per block
    constexpr int GE = 8;     // edges per thread
    constexpr int J  = CI * CO;
    __shared__ __align__(16) float ps_s[BE * PSTR];
    __shared__ float hs_s[BE * 33];
    __shared__ float nb_s[J];
    __shared__ int   dst_s[BE];

    const ull* WtU = (const ull*)((layer == 0) ? d_Wt0 : (layer == 1) ? d_Wt1 : d_Wt2);
    const float* hin = (layer == 1) ? d_h1 : d_h0;

    int e0 = blockIdx.x * BE;
    const float4* pg = (const float4*)(d_pseudo + (size_t)e0 * PSTR);
    float4* ps4 = (float4*)ps_s;
    for (int idx = threadIdx.x; idx < BE * (PSTR / 4); idx += NT) ps4[idx] = pg[idx];
    for (int idx = threadIdx.x; idx < BE * CI; idx += NT) {
        int el = idx >> 5, i = idx & 31;
        hs_s[el * 33 + i] = hin[(size_t)ei[e0 + el] * CI + i];
    }
    for (int idx = threadIdx.x; idx < BE; idx += NT) dst_s[idx] = ei[EE + e0 + idx];
    for (int idx = threadIdx.x; idx < J; idx += NT) nb_s[idx] = nb[idx];
    __syncthreads();

    int o = threadIdx.x % CO;
    int g = threadIdx.x / CO;
    const ull* psg2 = (const ull*)(ps_s + g * GE * PSTR);   // row stride 34 ulls
    const float* hsg = hs_s + g * GE * 33;
    float msg[GE];
    #pragma unroll
    for (int k = 0; k < GE; k++) msg[k] = 0.f;

    #pragma unroll 1
    for (int b4 = 0; b4 < CI / 4; b4++) {
        ull z2[4][GE];
        #pragma unroll
        for (int i = 0; i < 4; i++)
            #pragma unroll
            for (int k = 0; k < GE; k++) z2[i][k] = 0ull;

        // weight chunk for (b4, o): 4 consecutive ulls per p2, p2-stride = 32*CO ulls
        const ulonglong2* wp = (const ulonglong2*)(WtU + (size_t)(b4 * CO + o) * 4);
        #pragma unroll 2
        for (int p2 = 0; p2 < P2N; p2++) {
            ulonglong2 wa = wp[0];
            ulonglong2 wb = wp[1];
            ull w2[4] = {wa.x, wa.y, wb.x, wb.y};
            ull a2[GE];
            #pragma unroll
            for (int k = 0; k < GE; k++) a2[k] = psg2[k * (PSTR / 2) + p2];
            #pragma unroll
            for (int i = 0; i < 4; i++)
                #pragma unroll
                for (int k = 0; k < GE; k++) fma2(z2[i][k], a2[k], w2[i]);
            wp += 16 * CO;   // 32*CO ulls
        }
        #pragma unroll
        for (int i = 0; i < 4; i++) {
            float nbv = nb_s[(b4 * 4 + i) * CO + o];
            #pragma unroll
            for (int k = 0; k < GE; k++) {
                float z = red2(z2[i][k]) + nbv;
                msg[k] = fmaf(hsg[k * 33 + b4 * 4 + i], fmaxf(z, 0.f), msg[k]);
            }
        }
    }
    #pragma unroll
    for (int k = 0; k < GE; k++)
        atomicAdd(&d_aggr[(size_t)dst_s[g * GE + k] * CO + o], msg[k]);
}

// node update: h_out = relu(aggr/cnt + h_in @ root + bias); re-zeroes aggr for next layer
template <int CO>
__global__ void node_kernel(int layer, const float* __restrict__ root,
                            const float* __restrict__ bias, float* __restrict__ finalout,
                            int out_size) {
    __shared__ float4 root4[CI * CO / 4];
    __shared__ float  bias_s[CO];
    for (int i = threadIdx.x; i < CI * CO / 4; i += blockDim.x) root4[i] = ((const float4*)root)[i];
    for (int i = threadIdx.x; i < CO; i += blockDim.x) bias_s[i] = bias[i];
    __syncthreads();

    const float* hin = (layer == 1) ? d_h1 : d_h0;
    int v = blockIdx.x * blockDim.x + threadIdx.x;
    float inv = 1.f / (float)max(d_cnt[v], 1);

    float4 acc[CO / 4];
    #pragma unroll
    for (int q = 0; q < CO / 4; q++) {
        float4 ag = ((const float4*)(d_aggr + (size_t)v * CO))[q];
        acc[q].x = bias_s[4 * q]     + ag.x * inv;
        acc[q].y = bias_s[4 * q + 1] + ag.y * inv;
        acc[q].z = bias_s[4 * q + 2] + ag.z * inv;
        acc[q].w = bias_s[4 * q + 3] + ag.w * inv;
    }
    if (layer < 2) {
        float4 z4 = make_float4(0.f, 0.f, 0.f, 0.f);
        #pragma unroll
        for (int q = 0; q < CI / 4; q++) ((float4*)(d_aggr + (size_t)v * CI))[q] = z4;
    }
    float hv[CI];
    #pragma unroll
    for (int q = 0; q < CI / 4; q++) {
        float4 t = ((const float4*)(hin + (size_t)v * CI))[q];
        hv[4 * q] = t.x; hv[4 * q + 1] = t.y; hv[4 * q + 2] = t.z; hv[4 * q + 3] = t.w;
    }
    #pragma unroll
    for (int i = 0; i < CI; i++) {
        #pragma unroll
        for (int q = 0; q < CO / 4; q++) {
            float4 r = root4[i * (CO / 4) + q];
            acc[q].x = fmaf(hv[i], r.x, acc[q].x);
            acc[q].y = fmaf(hv[i], r.y, acc[q].y);
            acc[q].z = fmaf(hv[i], r.z, acc[q].z);
            acc[q].w = fmaf(hv[i], r.w, acc[q].w);
        }
    }
    float* hout = (layer == 0) ? d_h1 : (layer == 1) ? d_h0 : finalout;
    #pragma unroll
    for (int q = 0; q < CO / 4; q++) {
        float4 r;
        r.x = fmaxf(acc[q].x, 0.f); r.y = fmaxf(acc[q].y, 0.f);
        r.z = fmaxf(acc[q].z, 0.f); r.w = fmaxf(acc[q].w, 0.f);
        if (layer == 2) {
            int ofs = v * CO + 4 * q;
            if (ofs + 4 <= out_size) ((float4*)(hout + ofs))[0] = r;
        } else {
            ((float4*)(hout + (size_t)v * CO))[q] = r;
        }
    }
}

// remaining reference outputs (pos_skip, batch_skip) if the harness expects them
__global__ void tail_kernel(const float* __restrict__ pos_skip, const int* __restrict__ batch_skip,
                            float* __restrict__ out, int out_size) {
    int i = blockIdx.x * blockDim.x + threadIdx.x;
    int base = MM * 16;
    if (i < MM * 3 && base + i < out_size) out[base + i] = pos_skip[i];
    int base2 = base + MM * 3;
    if (i < MM && base2 + i < out_size) out[base2 + i] = (float)batch_skip[i];
}

// ---------------- launch ----------------
extern "C" void kernel_launch(void* const* d_in, const int* in_sizes, int n_in,
                              void* d_out, int out_size) {
    const float* x        = (const float*)d_in[0];
    const float* pos      = (const float*)d_in[1];
    const float* x_skip   = (const float*)d_in[3];
    const float* pos_skip = (const float*)d_in[4];
    const int*   batch_sk = (const int*)  d_in[5];
    const int*   ei       = (const int*)  d_in[6];
    const float* gt       = (const float*)d_in[7];
    const float* Wq_w = (const float*)d_in[8];   const float* Wq_b = (const float*)d_in[9];
    const float* Wk_w = (const float*)d_in[10];  const float* Wk_b = (const float*)d_in[11];
    const float* Wv_w = (const float*)d_in[12];  const float* Wv_b = (const float*)d_in[13];
    const float* ipw  = (const float*)d_in[14];  const float* ipb  = (const float*)d_in[15];
    const float* ow   = (const float*)d_in[16];  const float* ob   = (const float*)d_in[17];
    const float* nw0 = (const float*)d_in[18]; const float* nb0 = (const float*)d_in[19];
    const float* rt0 = (const float*)d_in[20]; const float* bs0 = (const float*)d_in[21];
    const float* nw1 = (const float*)d_in[22]; const float* nb1 = (const float*)d_in[23];
    const float* rt1 = (const float*)d_in[24]; const float* bs1 = (const float*)d_in[25];
    const float* nw2 = (const float*)d_in[26]; const float* nb2 = (const float*)d_in[27];
    const float* rt2 = (const float*)d_in[28]; const float* bs2 = (const float*)d_in[29];
    float* out = (float*)d_out;

    // launch #1: tokens + A/cc + weight re-layout
    setup_kernel<<<BB * TT + 1 + TRBLK, 256>>>(gt, Wk_w, Wk_b, Wv_w, Wv_b, ipw, ipb,
                                               Wq_w, Wq_b, nw0, nw1, nw2);
    // launch #2: s3 + knn (also zeroes cnt + aggr)
    mid_kernel<<<BB + MM / 128, 128>>>(x, pos, x_skip, pos_skip, ow);
    // launch #3: attention -> padded pseudo
    attn_kernel<<<EE / 256, 256>>>(ei, pos_skip, ob);

    // launch #4: dominant kernel (targeted ncu capture slot)
    edge_kernel<32><<<EE / 64, 256>>>(0, ei, nb0);
    deg_kernel<<<EE / 256, 256>>>(ei);
    node_kernel<32><<<MM / 256, 256>>>(0, rt0, bs0, nullptr, 0);   // zeroes aggr for L1
    edge_kernel<32><<<EE / 64, 256>>>(1, ei, nb1);
    node_kernel<32><<<MM / 256, 256>>>(1, rt1, bs1, nullptr, 0);   // zeroes aggr for L2
    edge_kernel<16><<<EE / 64, 128>>>(2, ei, nb2);
    node_kernel<16><<<MM / 256, 256>>>(2, rt2, bs2, out, out_size);

    tail_kernel<<<(MM * 3 + 255) / 256, 256>>>(pos_skip, batch_sk, out, out_size);
}

// round 11
// speedup vs baseline: 1.0851x; 1.0223x over previous
#include <cuda_runtime.h>

// ---------------- problem constants ----------------
#define BB   4
#define NPG  2048        // coarse nodes per graph
#define MM   65536       // skip nodes
#define MPG  16384
#define EE   131072      // edges
#define EPG  32768
#define TT   16          // tokens per graph
#define FIN  16
#define GDIM 1024
#define EMB  64
#define NH   4
#define HD   16
#define CI   32
#define PDIM 67          // 3 + 64
#define PSTR 68          // padded pseudo row stride (16B aligned, 34 pairs)
#define P2N  34          // p-pairs

typedef unsigned long long ull;

// ---------------- device scratch (no cudaMalloc allowed) ----------------
__device__ __align__(16) float d_pseudo[EE * PSTR];   // 35.6 MB, padded rows
__device__ float d_h0[MM * CI];
__device__ float d_h1[MM * CI];
__device__ float d_aggr[MM * CI];
__device__ int   d_cnt[MM];
// weight layout per layer: ull index ((p2*8 + b4)*CO + o)*4 + i  -> float pair (2*p2, 2*p2+1)
__device__ __align__(16) float d_Wt0[P2N * 1024 * 2];
__device__ __align__(16) float d_Wt1[P2N * 1024 * 2];
__device__ __align__(16) float d_Wt2[P2N * 512 * 2];
__device__ float d_A[EMB * 3];
__device__ float d_cc[EMB];
__device__ float d_K2[BB * TT * EMB];
__device__ float d_V2[BB * TT * EMB];
__device__ float d_U[BB * NH * TT * 3];
__device__ float d_s0[BB * NH * TT];
__device__ float d_OV[BB * NH * TT * EMB];

// ---------------- packed f32x2 helpers ----------------
__device__ __forceinline__ void fma2(ull& d, ull a, ull b) {
    asm("fma.rn.f32x2 %0, %1, %2, %0;" : "+l"(d) : "l"(a), "l"(b));
}
__device__ __forceinline__ float red2(ull v) {
    float lo, hi;
    asm("mov.b64 {%0, %1}, %2;" : "=f"(lo), "=f"(hi) : "l"(v));
    return lo + hi;
}

// ---------------- setup kernel: K2/V2 tokens + A/cc + weight re-layout, one launch ----------------
#define TRW0 (P2N * 1024)          // ull count, layer 0
#define TRW1 (P2N * 1024)
#define TRW2 (P2N * 512)
#define TRBLK ((TRW0 + TRW1 + TRW2) / 256)   // 340 blocks

__global__ void setup_kernel(const float* __restrict__ gt,
                             const float* __restrict__ Wk_w, const float* __restrict__ Wk_b,
                             const float* __restrict__ Wv_w, const float* __restrict__ Wv_b,
                             const float* __restrict__ ipw, const float* __restrict__ ipb,
                             const float* __restrict__ Wq_w, const float* __restrict__ Wq_b,
                             const float* __restrict__ nw0, const float* __restrict__ nw1,
                             const float* __restrict__ nw2) {
    int bid = blockIdx.x;
    if (bid < BB * TT) {
        // token projections, 4-way split over GDIM
        __shared__ float pK[4][EMB], pV[4][EMB];
        __shared__ float Kt[EMB], Vt[EMB];
        int bt = bid, tloc = bt % TT;
        int q = threadIdx.x >> 6, j = threadIdx.x & 63;
        const float* g  = gt + (size_t)bt * GDIM + q * 256;
        const float* wk = Wk_w + (size_t)j * GDIM + q * 256;
        const float* wv = Wv_w + (size_t)j * GDIM + q * 256;
        float sk = 0.f, sv = 0.f;
        for (int i = 0; i < 256; i += 4) {
            float4 gv = *(const float4*)(g + i);
            float4 k4 = *(const float4*)(wk + i);
            float4 v4 = *(const float4*)(wv + i);
            sk += gv.x * k4.x + gv.y * k4.y + gv.z * k4.z + gv.w * k4.w;
            sv += gv.x * v4.x + gv.y * v4.y + gv.z * v4.z + gv.w * v4.w;
        }
        pK[q][j] = sk; pV[q][j] = sv;
        __syncthreads();
        if (q == 0) {
            int i2 = j & ~1;
            float div = expf(-(float)i2 * (9.210340371976184f / (float)EMB));
            float ang = (float)tloc * div;
            float pe = (j & 1) ? cosf(ang) : sinf(ang);
            Kt[j] = pK[0][j] + pK[1][j] + pK[2][j] + pK[3][j] + Wk_b[j] + pe;
            Vt[j] = pV[0][j] + pV[1][j] + pV[2][j] + pV[3][j] + Wv_b[j] + pe;
        }
        __syncthreads();
        if (q == 0) {
            const float* wkr = ipw + (size_t)(EMB + j) * EMB;
            const float* wvr = ipw + (size_t)(2 * EMB + j) * EMB;
            float s2k = ipb[EMB + j], s2v = ipb[2 * EMB + j];
            for (int i = 0; i < EMB; i++) { s2k += Kt[i] * wkr[i]; s2v += Vt[i] * wvr[i]; }
            d_K2[bt * EMB + j] = s2k;
            d_V2[bt * EMB + j] = s2v;
        }
        return;
    }
    if (bid == BB * TT) {
        // A = wq @ Wq_w, cc = bq + wq @ Wq_b
        int t = threadIdx.x;
        for (int idx = t; idx < EMB * 3; idx += blockDim.x) {
            int j = idx / 3, p = idx % 3;
            float s = 0.f;
            for (int i = 0; i < EMB; i++) s += ipw[j * EMB + i] * Wq_w[i * 3 + p];
            d_A[idx] = s;
        }
        for (int j = t; j < EMB; j += blockDim.x) {
            float s = ipb[j];
            for (int i = 0; i < EMB; i++) s += ipw[j * EMB + i] * Wq_b[i];
            d_cc[j] = s;
        }
        return;
    }
    // weight re-layout
    int u = (bid - (BB * TT + 1)) * 256 + threadIdx.x;
    const float* nw; float* wt; int CO;
    if (u < TRW0)              { nw = nw0; wt = d_Wt0; CO = 32; }
    else if (u < TRW0 + TRW1)  { nw = nw1; wt = d_Wt1; CO = 32; u -= TRW0; }
    else                       { nw = nw2; wt = d_Wt2; CO = 16; u -= TRW0 + TRW1; }
    int i  = u & 3;
    int o  = (u >> 2) % CO;
    int b4 = ((u >> 2) / CO) & 7;
    int p2 = u / (32 * CO);
    int j  = (b4 * 4 + i) * CO + o;
    float lo = nw[j * PDIM + 2 * p2];
    float hi = (2 * p2 + 1 < PDIM) ? nw[j * PDIM + 2 * p2 + 1] : 0.f;
    wt[(size_t)u * 2]     = lo;
    wt[(size_t)u * 2 + 1] = hi;
}

// ---------------- mid kernel: s3 (blocks 0..3) + knn (blocks 4..) ----------------
__global__ void mid_kernel(const float* __restrict__ x, const float* __restrict__ pos,
                           const float* __restrict__ x_skip, const float* __restrict__ pos_skip,
                           const float* __restrict__ out_w) {
    __shared__ __align__(16) float4 sh4[NPG];   // {x, y, z, -0.5*|c|^2}
    int bid = blockIdx.x;
    if (bid < BB) {
        int b = bid, t = threadIdx.x;
        for (int idx = t; idx < NH * TT * 3; idx += blockDim.x) {
            int p = idx % 3; int ht = idx / 3; int h = ht / TT, tt = ht % TT;
            float s = 0.f;
            for (int d = 0; d < HD; d++)
                s += d_A[(h * HD + d) * 3 + p] * d_K2[(b * TT + tt) * EMB + h * HD + d];
            d_U[b * NH * TT * 3 + idx] = 0.25f * s;
        }
        for (int idx = t; idx < NH * TT; idx += blockDim.x) {
            int h = idx / TT, tt = idx % TT;
            float s = 0.f;
            for (int d = 0; d < HD; d++)
                s += d_cc[h * HD + d] * d_K2[(b * TT + tt) * EMB + h * HD + d];
            d_s0[b * NH * TT + idx] = 0.25f * s;
        }
        for (int idx = t; idx < NH * TT * EMB; idx += blockDim.x) {
            int j = idx % EMB; int ht = idx / EMB; int h = ht / TT, tt = ht % TT;
            float s = 0.f;
            for (int d = 0; d < HD; d++)
                s += out_w[j * EMB + h * HD + d] * d_V2[(b * TT + tt) * EMB + h * HD + d];
            d_OV[b * NH * TT * EMB + idx] = s;
        }
        return;
    }
    // ---- knn part: 128 threads/block, one skip node per thread ----
    int m = (bid - BB) * 128 + threadIdx.x;
    int b = m / MPG;
    const float* cp = pos + (size_t)b * NPG * 3;
    for (int j = threadIdx.x; j < NPG; j += 128) {
        float X = cp[j * 3], Y = cp[j * 3 + 1], Z = cp[j * 3 + 2];
        sh4[j] = make_float4(X, Y, Z, -0.5f * (X * X + Y * Y + Z * Z));
    }
    __syncthreads();

    // fold in: zero degree counter + layer-0 aggregation buffer
    d_cnt[m] = 0;
    float4 z4 = make_float4(0.f, 0.f, 0.f, 0.f);
    #pragma unroll
    for (int q = 0; q < CI / 4; q++) ((float4*)(d_aggr + (size_t)m * CI))[q] = z4;

    float px = pos_skip[m * 3], py = pos_skip[m * 3 + 1], pz = pos_skip[m * 3 + 2];
    float ps2 = px * px + py * py + pz * pz;
    // maximize s = dot - 0.5*|c|^2  (equiv. minimize squared distance)
    float b0 = -1e30f, b1 = -1e30f, b2 = -1e30f;
    int i0 = 0, i1 = 0, i2 = 0;
    #pragma unroll 4
    for (int j = 0; j < NPG; j++) {
        float4 c = sh4[j];
        float s = fmaf(px, c.x, fmaf(py, c.y, fmaf(pz, c.z, c.w)));
        if (s > b2) {
            if (s > b1) {
                b2 = b1; i2 = i1;
                if (s > b0) { b1 = b0; i1 = i0; b0 = s; i0 = j; }
                else        { b1 = s;  i1 = j; }
            } else { b2 = s; i2 = j; }
        }
    }
    float d0 = fmaf(-2.f, b0, ps2);
    float d1 = fmaf(-2.f, b1, ps2);
    float d2 = fmaf(-2.f, b2, ps2);
    float w0 = 1.f / fmaxf(d0, 1e-16f);
    float w1 = 1.f / fmaxf(d1, 1e-16f);
    float w2 = 1.f / fmaxf(d2, 1e-16f);
    float inv = 1.f / (w0 + w1 + w2);
    const float* x0 = x + (size_t)(b * NPG + i0) * FIN;
    const float* x1 = x + (size_t)(b * NPG + i1) * FIN;
    const float* x2 = x + (size_t)(b * NPG + i2) * FIN;
    const float* xs = x_skip + (size_t)m * FIN;
    float* h = d_h0 + (size_t)m * CI;
    #pragma unroll
    for (int f = 0; f < FIN; f++) {
        h[f]       = (w0 * x0[f] + w1 * x1[f] + w2 * x2[f]) * inv;
        h[FIN + f] = xs[f];
    }
}

// ---------------- degree ----------------
__global__ void deg_kernel(const int* __restrict__ ei) {
    int e = blockIdx.x * blockDim.x + threadIdx.x;
    if (e < EE) atomicAdd(&d_cnt[ei[EE + e]], 1);
}

// ---------------- stage B: per-edge attention -> pseudo [E,68(padded)] ----------------
__global__ void attn_kernel(const int* __restrict__ ei, const float* __restrict__ pos_skip,
                            const float* __restrict__ out_b) {
    __shared__ float4 sOV4[NH * TT * EMB / 4];
    __shared__ float sU[NH * TT * 3], sS0[NH * TT], sOB[EMB];
    int e = blockIdx.x * blockDim.x + threadIdx.x;
    int b = blockIdx.x / (EPG / 256);
    float* sOV = (float*)sOV4;
    for (int i = threadIdx.x; i < NH * TT * EMB; i += 256) sOV[i] = d_OV[b * NH * TT * EMB + i];
    for (int i = threadIdx.x; i < NH * TT * 3;  i += 256) sU[i]  = d_U[b * NH * TT * 3 + i];
    for (int i = threadIdx.x; i < NH * TT;      i += 256) sS0[i] = d_s0[b * NH * TT + i];
    for (int i = threadIdx.x; i < EMB;          i += 256) sOB[i] = out_b[i];
    __syncthreads();
    int s = ei[e], d = ei[EE + e];
    float sx = pos_skip[s * 3], sy = pos_skip[s * 3 + 1], sz = pos_skip[s * 3 + 2];
    float dx = pos_skip[d * 3], dy = pos_skip[d * 3 + 1], dz = pos_skip[d * 3 + 2];
    float epx = 0.5f * (dx + sx), epy = 0.5f * (dy + sy), epz = 0.5f * (dz + sz);
    float4 o4[EMB / 4];
    #pragma unroll
    for (int q = 0; q < EMB / 4; q++) {
        o4[q].x = sOB[4 * q]; o4[q].y = sOB[4 * q + 1];
        o4[q].z = sOB[4 * q + 2]; o4[q].w = sOB[4 * q + 3];
    }
    #pragma unroll
    for (int h = 0; h < NH; h++) {
        float sc[TT];
        float mx = -1e30f;
        #pragma unroll
        for (int t = 0; t < TT; t++) {
            int ht = h * TT + t;
            sc[t] = sS0[ht] + epx * sU[ht * 3] + epy * sU[ht * 3 + 1] + epz * sU[ht * 3 + 2];
            mx = fmaxf(mx, sc[t]);
        }
        float se = 0.f;
        #pragma unroll
        for (int t = 0; t < TT; t++) { sc[t] = __expf(sc[t] - mx); se += sc[t]; }
        float inv = 1.f / se;
        #pragma unroll
        for (int t = 0; t < TT; t++) {
            float a = sc[t] * inv;
            const float4* row = sOV4 + (h * TT + t) * (EMB / 4);
            #pragma unroll
            for (int q = 0; q < EMB / 4; q++) {
                float4 v = row[q];
                o4[q].x += a * v.x; o4[q].y += a * v.y;
                o4[q].z += a * v.z; o4[q].w += a * v.w;
            }
        }
    }
    float* pd = d_pseudo + (size_t)e * PSTR;
    pd[0] = dx - sx; pd[1] = dy - sy; pd[2] = dz - sz;
    #pragma unroll
    for (int q = 0; q < EMB / 4; q++) {
        pd[3 + 4 * q] = o4[q].x; pd[4 + 4 * q] = o4[q].y;
        pd[5 + 4 * q] = o4[q].z; pd[6 + 4 * q] = o4[q].w;
    }
    pd[67] = 0.f;   // pair padding
}

// ---------------- stage C: fused edge MLP (packed f32x2, 2-p2 LDS.128) ----------------
template <int CO>
__global__ void __launch_bounds__(CO * 8)
edge_kernel(int layer, const int* __restrict__ ei, const float* __restrict__ nb) {
    constexpr int NT = CO * 8;
    constexpr int BE = 64;    // edges per block
    constexpr int GE = 8;     // edges per thread
    constexpr int J  = CI * CO;
    __shared__ __align__(16) float ps_s[BE * PSTR];
    __shared__ float hs_s[BE * 33];
    __shared__ float nb_s[J];
    __shared__ int   dst_s[BE];

    const ull* WtU = (const ull*)((layer == 0) ? d_Wt0 : (layer == 1) ? d_Wt1 : d_Wt2);
    const float* hin = (layer == 1) ? d_h1 : d_h0;

    int e0 = blockIdx.x * BE;
    const float4* pg = (const float4*)(d_pseudo + (size_t)e0 * PSTR);
    float4* ps4 = (float4*)ps_s;
    for (int idx = threadIdx.x; idx < BE * (PSTR / 4); idx += NT) ps4[idx] = pg[idx];
    for (int idx = threadIdx.x; idx < BE * CI; idx += NT) {
        int el = idx >> 5, i = idx & 31;
        hs_s[el * 33 + i] = hin[(size_t)ei[e0 + el] * CI + i];
    }
    for (int idx = threadIdx.x; idx < BE; idx += NT) dst_s[idx] = ei[EE + e0 + idx];
    for (int idx = threadIdx.x; idx < J; idx += NT) nb_s[idx] = nb[idx];
    __syncthreads();

    int o = threadIdx.x % CO;
    int g = threadIdx.x / CO;
    const ull* psg2 = (const ull*)(ps_s + g * GE * PSTR);   // row stride PSTR/2 = 34 ulls
    const float* hsg = hs_s + g * GE * 33;
    float msg[GE];
    #pragma unroll
    for (int k = 0; k < GE; k++) msg[k] = 0.f;

    #pragma unroll 1
    for (int b4 = 0; b4 < CI / 4; b4++) {
        ull z2[4][GE];
        #pragma unroll
        for (int i = 0; i < 4; i++)
            #pragma unroll
            for (int k = 0; k < GE; k++) z2[i][k] = 0ull;

        // weight chunk for (b4, o): 4 consecutive ulls per p2, p2-stride = 32*CO ulls
        const ulonglong2* wp = (const ulonglong2*)(WtU + (size_t)(b4 * CO + o) * 4);
        #pragma unroll 1
        for (int p2g = 0; p2g < P2N / 2; p2g++) {
            // even pair (p2 = 2*p2g) and odd pair (p2 = 2*p2g+1) weights
            ulonglong2 wa0 = wp[0],       wa1 = wp[1];
            ulonglong2 wb0 = wp[16 * CO], wb1 = wp[16 * CO + 1];
            ull wa[4] = {wa0.x, wa0.y, wa1.x, wa1.y};
            ull wb[4] = {wb0.x, wb0.y, wb1.x, wb1.y};
            #pragma unroll
            for (int k = 0; k < GE; k++) {
                // one LDS.128: a-pairs for both p2 (broadcast across warp)
                ulonglong2 a = *(const ulonglong2*)(psg2 + k * (PSTR / 2) + 2 * p2g);
                #pragma unroll
                for (int i = 0; i < 4; i++) {
                    fma2(z2[i][k], a.x, wa[i]);
                    fma2(z2[i][k], a.y, wb[i]);
                }
            }
            wp += 32 * CO;   // advance 2 p2 (64*CO ulls)
        }
        #pragma unroll
        for (int i = 0; i < 4; i++) {
            float nbv = nb_s[(b4 * 4 + i) * CO + o];
            #pragma unroll
            for (int k = 0; k < GE; k++) {
                float z = red2(z2[i][k]) + nbv;
                msg[k] = fmaf(hsg[k * 33 + b4 * 4 + i], fmaxf(z, 0.f), msg[k]);
            }
        }
    }
    #pragma unroll
    for (int k = 0; k < GE; k++)
        atomicAdd(&d_aggr[(size_t)dst_s[g * GE + k] * CO + o], msg[k]);
}

// node update: h_out = relu(aggr/cnt + h_in @ root + bias); re-zeroes aggr for next layer
template <int CO>
__global__ void node_kernel(int layer, const float* __restrict__ root,
                            const float* __restrict__ bias, float* __restrict__ finalout,
                            int out_size) {
    __shared__ float4 root4[CI * CO / 4];
    __shared__ float  bias_s[CO];
    for (int i = threadIdx.x; i < CI * CO / 4; i += blockDim.x) root4[i] = ((const float4*)root)[i];
    for (int i = threadIdx.x; i < CO; i += blockDim.x) bias_s[i] = bias[i];
    __syncthreads();

    const float* hin = (layer == 1) ? d_h1 : d_h0;
    int v = blockIdx.x * blockDim.x + threadIdx.x;
    float inv = 1.f / (float)max(d_cnt[v], 1);

    float4 acc[CO / 4];
    #pragma unroll
    for (int q = 0; q < CO / 4; q++) {
        float4 ag = ((const float4*)(d_aggr + (size_t)v * CO))[q];
        acc[q].x = bias_s[4 * q]     + ag.x * inv;
        acc[q].y = bias_s[4 * q + 1] + ag.y * inv;
        acc[q].z = bias_s[4 * q + 2] + ag.z * inv;
        acc[q].w = bias_s[4 * q + 3] + ag.w * inv;
    }
    if (layer < 2) {
        float4 z4 = make_float4(0.f, 0.f, 0.f, 0.f);
        #pragma unroll
        for (int q = 0; q < CI / 4; q++) ((float4*)(d_aggr + (size_t)v * CI))[q] = z4;
    }
    float hv[CI];
    #pragma unroll
    for (int q = 0; q < CI / 4; q++) {
        float4 t = ((const float4*)(hin + (size_t)v * CI))[q];
        hv[4 * q] = t.x; hv[4 * q + 1] = t.y; hv[4 * q + 2] = t.z; hv[4 * q + 3] = t.w;
    }
    #pragma unroll
    for (int i = 0; i < CI; i++) {
        #pragma unroll
        for (int q = 0; q < CO / 4; q++) {
            float4 r = root4[i * (CO / 4) + q];
            acc[q].x = fmaf(hv[i], r.x, acc[q].x);
            acc[q].y = fmaf(hv[i], r.y, acc[q].y);
            acc[q].z = fmaf(hv[i], r.z, acc[q].z);
            acc[q].w = fmaf(hv[i], r.w, acc[q].w);
        }
    }
    float* hout = (layer == 0) ? d_h1 : (layer == 1) ? d_h0 : finalout;
    #pragma unroll
    for (int q = 0; q < CO / 4; q++) {
        float4 r;
        r.x = fmaxf(acc[q].x, 0.f); r.y = fmaxf(acc[q].y, 0.f);
        r.z = fmaxf(acc[q].z, 0.f); r.w = fmaxf(acc[q].w, 0.f);
        if (layer == 2) {
            int ofs = v * CO + 4 * q;
            if (ofs + 4 <= out_size) ((float4*)(hout + ofs))[0] = r;
        } else {
            ((float4*)(hout + (size_t)v * CO))[q] = r;
        }
    }
}

// remaining reference outputs (pos_skip, batch_skip) if the harness expects them
__global__ void tail_kernel(const float* __restrict__ pos_skip, const int* __restrict__ batch_skip,
                            float* __restrict__ out, int out_size) {
    int i = blockIdx.x * blockDim.x + threadIdx.x;
    int base = MM * 16;
    if (i < MM * 3 && base + i < out_size) out[base + i] = pos_skip[i];
    int base2 = base + MM * 3;
    if (i < MM && base2 + i < out_size) out[base2 + i] = (float)batch_skip[i];
}

// ---------------- launch ----------------
extern "C" void kernel_launch(void* const* d_in, const int* in_sizes, int n_in,
                              void* d_out, int out_size) {
    const float* x        = (const float*)d_in[0];
    const float* pos      = (const float*)d_in[1];
    const float* x_skip   = (const float*)d_in[3];
    const float* pos_skip = (const float*)d_in[4];
    const int*   batch_sk = (const int*)  d_in[5];
    const int*   ei       = (const int*)  d_in[6];
    const float* gt       = (const float*)d_in[7];
    const float* Wq_w = (const float*)d_in[8];   const float* Wq_b = (const float*)d_in[9];
    const float* Wk_w = (const float*)d_in[10];  const float* Wk_b = (const float*)d_in[11];
    const float* Wv_w = (const float*)d_in[12];  const float* Wv_b = (const float*)d_in[13];
    const float* ipw  = (const float*)d_in[14];  const float* ipb  = (const float*)d_in[15];
    const float* ow   = (const float*)d_in[16];  const float* ob   = (const float*)d_in[17];
    const float* nw0 = (const float*)d_in[18]; const float* nb0 = (const float*)d_in[19];
    const float* rt0 = (const float*)d_in[20]; const float* bs0 = (const float*)d_in[21];
    const float* nw1 = (const float*)d_in[22]; const float* nb1 = (const float*)d_in[23];
    const float* rt1 = (const float*)d_in[24]; const float* bs1 = (const float*)d_in[25];
    const float* nw2 = (const float*)d_in[26]; const float* nb2 = (const float*)d_in[27];
    const float* rt2 = (const float*)d_in[28]; const float* bs2 = (const float*)d_in[29];
    float* out = (float*)d_out;

    // launch #1: tokens + A/cc + weight re-layout
    setup_kernel<<<BB * TT + 1 + TRBLK, 256>>>(gt, Wk_w, Wk_b, Wv_w, Wv_b, ipw, ipb,
                                               Wq_w, Wq_b, nw0, nw1, nw2);
    // launch #2: s3 + knn (also zeroes cnt + aggr)
    mid_kernel<<<BB + MM / 128, 128>>>(x, pos, x_skip, pos_skip, ow);
    // launch #3: attention -> padded pseudo
    attn_kernel<<<EE / 256, 256>>>(ei, pos_skip, ob);

    // launch #4: dominant kernel (targeted ncu capture slot)
    edge_kernel<32><<<EE / 64, 256>>>(0, ei, nb0);
    deg_kernel<<<EE / 256, 256>>>(ei);
    node_kernel<32><<<MM / 256, 256>>>(0, rt0, bs0, nullptr, 0);   // zeroes aggr for L1
    edge_kernel<32><<<EE / 64, 256>>>(1, ei, nb1);
    node_kernel<32><<<MM / 256, 256>>>(1, rt1, bs1, nullptr, 0);   // zeroes aggr for L2
    edge_kernel<16><<<EE / 64, 128>>>(2, ei, nb2);
    node_kernel<16><<<MM / 256, 256>>>(2, rt2, bs2, out, out_size);

    tail_kernel<<<(MM * 3 + 255) / 256, 256>>>(pos_skip, batch_sk, out, out_size);
}